// round 4
// baseline (speedup 1.0000x reference)
#include <cuda_runtime.h>
#include <cuda_bf16.h>
#include <math.h>
#include <stdint.h>

#define D_MODEL 1024
#define S_LEN   2048
#define BATCH   4
#define NHEAD   16
#define DKH     64
#define ROWS    (BATCH * S_LEN)   // 8192
#define KAUG    (3 * D_MODEL)     // 3072 (hi | lo | hi  vs  hi | hi | lo)

// Scratch (static device globals — no runtime allocation)
__device__ float g_q[ROWS * D_MODEL];
__device__ float g_k[ROWS * D_MODEL];
__device__ float g_v[ROWS * D_MODEL];
__device__ float g_att[ROWS * D_MODEL];
__device__ __nv_bfloat16 g_xaug[(size_t)ROWS * KAUG];           // reused for att_aug
__device__ __nv_bfloat16 g_waug[4][(size_t)D_MODEL * KAUG];

// ---------------------------------------------------------------------------
// fp32 -> split-bf16 augmented layout.
// AMODE (activations): segments [hi | lo | hi]
// !AMODE (weights):    segments [hi | hi | lo]
// sum_k' A'[m][k'] * B'[n][k'] = hA.hB + lA.hB + hA.lB  ~= a*b (err ~2^-16)
// ---------------------------------------------------------------------------
template <bool AMODE>
__global__ __launch_bounds__(256)
void conv_aug_kernel(const float* __restrict__ in, __nv_bfloat16* __restrict__ out,
                     int nrows)
{
    const int idx = blockIdx.x * blockDim.x + threadIdx.x;   // one per 4 elems
    const int kq = idx & (D_MODEL / 4 - 1);
    const int r  = idx >> 8;                                  // / (D_MODEL/4)
    if (r >= nrows) return;

    float4 v = *(const float4*)(in + (size_t)r * D_MODEL + kq * 4);
    __nv_bfloat16 h0 = __float2bfloat16_rn(v.x);
    __nv_bfloat16 h1 = __float2bfloat16_rn(v.y);
    __nv_bfloat16 h2 = __float2bfloat16_rn(v.z);
    __nv_bfloat16 h3 = __float2bfloat16_rn(v.w);
    __nv_bfloat16 l0 = __float2bfloat16_rn(v.x - __bfloat162float(h0));
    __nv_bfloat16 l1 = __float2bfloat16_rn(v.y - __bfloat162float(h1));
    __nv_bfloat16 l2 = __float2bfloat16_rn(v.z - __bfloat162float(h2));
    __nv_bfloat16 l3 = __float2bfloat16_rn(v.w - __bfloat162float(h3));

    __nv_bfloat162 hi01; hi01.x = h0; hi01.y = h1;
    __nv_bfloat162 hi23; hi23.x = h2; hi23.y = h3;
    __nv_bfloat162 lo01; lo01.x = l0; lo01.y = l1;
    __nv_bfloat162 lo23; lo23.x = l2; lo23.y = l3;

    const size_t base = (size_t)r * KAUG + kq * 4;
    __nv_bfloat162* o0 = (__nv_bfloat162*)(out + base);
    __nv_bfloat162* o1 = (__nv_bfloat162*)(out + base + D_MODEL);
    __nv_bfloat162* o2 = (__nv_bfloat162*)(out + base + 2 * D_MODEL);
    o0[0] = hi01; o0[1] = hi23;
    if (AMODE) { o1[0] = lo01; o1[1] = lo23; o2[0] = hi01; o2[1] = hi23; }
    else       { o1[0] = hi01; o1[1] = hi23; o2[0] = lo01; o2[1] = lo23; }
}

// ---------------------------------------------------------------------------
// bf16 mma.sync GEMM:  Y[m][n] = sum_k A[m][k]*B[n][k] + bias[n]  (fp32 out)
// A:[M x KAUG], B:[N x KAUG] bf16 row-major.  BM=BN=128, BK=32, 256 threads,
// 8 warps in 2x4, warp tile 64x32, m16n8k16.  cp.async 2-stage pipeline.
// Smem rows strided 80B (32 bf16 + 16B pad) -> conflict-free ldmatrix.
// ---------------------------------------------------------------------------
#define SMSTRIDE 80
#define TILEBYTES (128 * SMSTRIDE)   // 10240 per operand per stage

__device__ __forceinline__ void cp_async16(uint32_t s, const void* g) {
    asm volatile("cp.async.cg.shared.global [%0], [%1], 16;\n" :: "r"(s), "l"(g));
}
__device__ __forceinline__ void cp_commit() {
    asm volatile("cp.async.commit_group;\n");
}
template <int N>
__device__ __forceinline__ void cp_wait() {
    asm volatile("cp.async.wait_group %0;\n" :: "n"(N));
}
__device__ __forceinline__ void ldsm_x4(uint32_t& r0, uint32_t& r1, uint32_t& r2,
                                        uint32_t& r3, uint32_t addr) {
    asm volatile("ldmatrix.sync.aligned.m8n8.x4.shared.b16 {%0,%1,%2,%3}, [%4];\n"
                 : "=r"(r0), "=r"(r1), "=r"(r2), "=r"(r3) : "r"(addr));
}
__device__ __forceinline__ void mma16816(float* c, const uint32_t* a, const uint32_t* b) {
    asm volatile(
        "mma.sync.aligned.m16n8k16.row.col.f32.bf16.bf16.f32 "
        "{%0,%1,%2,%3}, {%4,%5,%6,%7}, {%8,%9}, {%0,%1,%2,%3};\n"
        : "+f"(c[0]), "+f"(c[1]), "+f"(c[2]), "+f"(c[3])
        : "r"(a[0]), "r"(a[1]), "r"(a[2]), "r"(a[3]), "r"(b[0]), "r"(b[1]));
}

template <bool HEAD_MAJOR>
__global__ __launch_bounds__(256)
void gemm_mma_kernel(const __nv_bfloat16* __restrict__ A,
                     const __nv_bfloat16* __restrict__ B,
                     const float* __restrict__ bias, float* __restrict__ Y)
{
    __shared__ uint8_t sm[2 * 2 * TILEBYTES];   // [stage][A|B][128][80]

    const int tid  = threadIdx.x;
    const int lane = tid & 31;
    const int warp = tid >> 5;
    const int wm   = warp >> 2;     // 0..1
    const int wn   = warp & 3;      // 0..3
    const int row0 = blockIdx.x * 128;
    const int col0 = blockIdx.y * 128;

    const uint32_t smem_u32 = (uint32_t)__cvta_generic_to_shared(sm);

    // cp.async mapping: 512 x 16B chunks per tile; thread handles 2 per operand.
    const int c0r = tid >> 2, c0c = (tid & 3);          // chunk tid
    const int c1r = (tid + 256) >> 2, c1c = c0c;        // chunk tid+256

    float acc[4][4][4];
#pragma unroll
    for (int i = 0; i < 4; i++)
#pragma unroll
        for (int j = 0; j < 4; j++)
#pragma unroll
            for (int q = 0; q < 4; q++) acc[i][j][q] = 0.f;

    auto issue_stage = [&](int stage, int kt) {
        const uint32_t sA = smem_u32 + stage * 2 * TILEBYTES;
        const uint32_t sB = sA + TILEBYTES;
        const int kelem = kt * 32;
        cp_async16(sA + c0r * SMSTRIDE + c0c * 16,
                   A + (size_t)(row0 + c0r) * KAUG + kelem + c0c * 8);
        cp_async16(sA + c1r * SMSTRIDE + c1c * 16,
                   A + (size_t)(row0 + c1r) * KAUG + kelem + c1c * 8);
        cp_async16(sB + c0r * SMSTRIDE + c0c * 16,
                   B + (size_t)(col0 + c0r) * KAUG + kelem + c0c * 8);
        cp_async16(sB + c1r * SMSTRIDE + c1c * 16,
                   B + (size_t)(col0 + c1r) * KAUG + kelem + c1c * 8);
        cp_commit();
    };

    constexpr int NK = KAUG / 32;   // 96
    issue_stage(0, 0);

    for (int kt = 0; kt < NK; kt++) {
        if (kt + 1 < NK) {
            issue_stage((kt + 1) & 1, kt + 1);
            cp_wait<1>();
        } else {
            cp_wait<0>();
        }
        __syncthreads();

        const uint32_t sA = smem_u32 + (kt & 1) * 2 * TILEBYTES;
        const uint32_t sB = sA + TILEBYTES;

#pragma unroll
        for (int ks = 0; ks < 2; ks++) {
            uint32_t a[4][4];
            const int arow  = wm * 64 + (lane & 15);
            const int abyte = ks * 32 + (lane >> 4) * 16;
#pragma unroll
            for (int mf = 0; mf < 4; mf++)
                ldsm_x4(a[mf][0], a[mf][1], a[mf][2], a[mf][3],
                        sA + (arow + mf * 16) * SMSTRIDE + abyte);

            uint32_t b[4][2];
            const int brow  = ((lane >> 4) & 1) * 8 + (lane & 7);
            const int bbyte = ks * 32 + ((lane >> 3) & 1) * 16;
#pragma unroll
            for (int bf = 0; bf < 2; bf++) {
                uint32_t t0, t1, t2, t3;
                ldsm_x4(t0, t1, t2, t3,
                        sB + (wn * 32 + bf * 16 + brow) * SMSTRIDE + bbyte);
                b[bf * 2 + 0][0] = t0; b[bf * 2 + 0][1] = t1;
                b[bf * 2 + 1][0] = t2; b[bf * 2 + 1][1] = t3;
            }

#pragma unroll
            for (int mf = 0; mf < 4; mf++)
#pragma unroll
                for (int nf = 0; nf < 4; nf++)
                    mma16816(acc[mf][nf], a[mf], b[nf]);
        }
        __syncthreads();
    }

    // Epilogue: + bias, write fp32 (optionally head-major scatter)
#pragma unroll
    for (int mf = 0; mf < 4; mf++) {
        const int r0 = row0 + wm * 64 + mf * 16 + (lane >> 2);
#pragma unroll
        for (int nf = 0; nf < 4; nf++) {
            const int c = col0 + wn * 32 + nf * 8 + (lane & 3) * 2;
            const float b0 = bias[c], b1 = bias[c + 1];
            float2 v0 = make_float2(acc[mf][nf][0] + b0, acc[mf][nf][1] + b1);
            float2 v1 = make_float2(acc[mf][nf][2] + b0, acc[mf][nf][3] + b1);
            if (HEAD_MAJOR) {
                const int h = c >> 6, d = c & 63;
                const int bb0 = r0 >> 11, s0 = r0 & 2047;
                *(float2*)(Y + ((size_t)((bb0 * NHEAD + h) * S_LEN + s0)) * DKH + d) = v0;
                const int r1 = r0 + 8;
                const int bb1 = r1 >> 11, s1 = r1 & 2047;
                *(float2*)(Y + ((size_t)((bb1 * NHEAD + h) * S_LEN + s1)) * DKH + d) = v1;
            } else {
                *(float2*)(Y + (size_t)r0 * D_MODEL + c) = v0;
                *(float2*)(Y + (size_t)(r0 + 8) * D_MODEL + c) = v1;
            }
        }
    }
}

// ---------------------------------------------------------------------------
// Flash attention (fp32 SIMT) — unchanged.
// ---------------------------------------------------------------------------
__global__ __launch_bounds__(256)
void attn_kernel(const float* __restrict__ Q, const float* __restrict__ K,
                 const float* __restrict__ V, float* __restrict__ O)
{
    __shared__ float Qt[64][64];
    __shared__ float Kt[64][64];
    __shared__ float Vs[64][64];
    float (*Ps)[64] = Kt;

    const int tid = threadIdx.x;
    const int tx  = tid & 15;
    const int ty  = tid >> 4;
    const int bh  = blockIdx.y;
    const int q0  = blockIdx.x * 64;

    const float* qb = Q + ((size_t)bh * S_LEN + q0) * DKH;
    const float* kb = K + (size_t)bh * S_LEN * DKH;
    const float* vb = V + (size_t)bh * S_LEN * DKH;

    const int lr = tid >> 2;
    const int lc = (tid & 3) << 4;

#pragma unroll
    for (int u = 0; u < 4; u++) {
        float4 v = *(const float4*)(qb + (size_t)lr * DKH + lc + u * 4);
        Qt[lc + u * 4 + 0][lr] = v.x; Qt[lc + u * 4 + 1][lr] = v.y;
        Qt[lc + u * 4 + 2][lr] = v.z; Qt[lc + u * 4 + 3][lr] = v.w;
    }

    float o[4][4];
    float m[4], l[4];
#pragma unroll
    for (int i = 0; i < 4; i++) {
        m[i] = -1e30f; l[i] = 0.f;
#pragma unroll
        for (int j = 0; j < 4; j++) o[i][j] = 0.f;
    }
    const float scale = 0.125f;

    for (int kt = 0; kt < S_LEN; kt += 64) {
        __syncthreads();

#pragma unroll
        for (int u = 0; u < 4; u++) {
            float4 v = *(const float4*)(kb + (size_t)(kt + lr) * DKH + lc + u * 4);
            Kt[lc + u * 4 + 0][lr] = v.x; Kt[lc + u * 4 + 1][lr] = v.y;
            Kt[lc + u * 4 + 2][lr] = v.z; Kt[lc + u * 4 + 3][lr] = v.w;
            float4 w = *(const float4*)(vb + (size_t)(kt + lr) * DKH + lc + u * 4);
            *(float4*)&Vs[lr][lc + u * 4] = w;
        }
        __syncthreads();

        float s[4][4];
#pragma unroll
        for (int i = 0; i < 4; i++)
#pragma unroll
            for (int j = 0; j < 4; j++) s[i][j] = 0.f;

#pragma unroll 8
        for (int d = 0; d < DKH; d++) {
            float a[4], b[4];
            *(float4*)a = *(const float4*)&Qt[d][ty * 4];
            *(float4*)b = *(const float4*)&Kt[d][tx * 4];
#pragma unroll
            for (int i = 0; i < 4; i++)
#pragma unroll
                for (int j = 0; j < 4; j++) s[i][j] += a[i] * b[j];
        }
        __syncthreads();

#pragma unroll
        for (int i = 0; i < 4; i++) {
            float tmax = -1e30f;
#pragma unroll
            for (int j = 0; j < 4; j++) {
                s[i][j] *= scale;
                tmax = fmaxf(tmax, s[i][j]);
            }
            tmax = fmaxf(tmax, __shfl_xor_sync(0xffffffffu, tmax, 1));
            tmax = fmaxf(tmax, __shfl_xor_sync(0xffffffffu, tmax, 2));
            tmax = fmaxf(tmax, __shfl_xor_sync(0xffffffffu, tmax, 4));
            tmax = fmaxf(tmax, __shfl_xor_sync(0xffffffffu, tmax, 8));
            const float mn   = fmaxf(m[i], tmax);
            const float corr = __expf(m[i] - mn);
            m[i] = mn;
            float p[4], ls = 0.f;
#pragma unroll
            for (int j = 0; j < 4; j++) { p[j] = __expf(s[i][j] - mn); ls += p[j]; }
            ls += __shfl_xor_sync(0xffffffffu, ls, 1);
            ls += __shfl_xor_sync(0xffffffffu, ls, 2);
            ls += __shfl_xor_sync(0xffffffffu, ls, 4);
            ls += __shfl_xor_sync(0xffffffffu, ls, 8);
            l[i] = l[i] * corr + ls;
#pragma unroll
            for (int j = 0; j < 4; j++) o[i][j] *= corr;
            *(float4*)&Ps[ty * 4 + i][tx * 4] = make_float4(p[0], p[1], p[2], p[3]);
        }
        __syncthreads();

#pragma unroll 4
        for (int k0 = 0; k0 < 64; k0 += 4) {
            float av[4][4];
#pragma unroll
            for (int i = 0; i < 4; i++) {
                float4 t = *(const float4*)&Ps[ty * 4 + i][k0];
                av[i][0] = t.x; av[i][1] = t.y; av[i][2] = t.z; av[i][3] = t.w;
            }
#pragma unroll
            for (int kk = 0; kk < 4; kk++) {
                float b[4];
                *(float4*)b = *(const float4*)&Vs[k0 + kk][tx * 4];
#pragma unroll
                for (int i = 0; i < 4; i++)
#pragma unroll
                    for (int j = 0; j < 4; j++) o[i][j] += av[i][kk] * b[j];
            }
        }
    }

    const int bb = bh >> 4, h = bh & 15;
#pragma unroll
    for (int i = 0; i < 4; i++) {
        const float inv = 1.f / l[i];
        const size_t row = (size_t)bb * S_LEN + q0 + ty * 4 + i;
        float4 v = make_float4(o[i][0] * inv, o[i][1] * inv,
                               o[i][2] * inv, o[i][3] * inv);
        *(float4*)(O + row * D_MODEL + h * DKH + tx * 4) = v;
    }
}

// ---------------------------------------------------------------------------
extern "C" void kernel_launch(void* const* d_in, const int* in_sizes, int n_in,
                              void* d_out, int out_size)
{
    (void)in_sizes; (void)n_in; (void)out_size;
    const float* x  = (const float*)d_in[0];
    const float* wq = (const float*)d_in[1];
    const float* bq = (const float*)d_in[2];
    const float* wk = (const float*)d_in[3];
    const float* bk = (const float*)d_in[4];
    const float* wv = (const float*)d_in[5];
    const float* bv = (const float*)d_in[6];
    const float* wo = (const float*)d_in[7];
    const float* bo = (const float*)d_in[8];
    float* out = (float*)d_out;

    float *q, *k, *v, *att;
    __nv_bfloat16 *xaug, *waug;
    cudaGetSymbolAddress((void**)&q,    g_q);
    cudaGetSymbolAddress((void**)&k,    g_k);
    cudaGetSymbolAddress((void**)&v,    g_v);
    cudaGetSymbolAddress((void**)&att,  g_att);
    cudaGetSymbolAddress((void**)&xaug, g_xaug);
    cudaGetSymbolAddress((void**)&waug, g_waug);
    const size_t wstride = (size_t)D_MODEL * KAUG;

    // Weight + activation split-bf16 conversions
    const int wblocks = (D_MODEL * (D_MODEL / 4)) / 256;   // 1024
    conv_aug_kernel<false><<<wblocks, 256>>>(wq, waug + 0 * wstride, D_MODEL);
    conv_aug_kernel<false><<<wblocks, 256>>>(wk, waug + 1 * wstride, D_MODEL);
    conv_aug_kernel<false><<<wblocks, 256>>>(wv, waug + 2 * wstride, D_MODEL);
    conv_aug_kernel<false><<<wblocks, 256>>>(wo, waug + 3 * wstride, D_MODEL);
    const int xblocks = (ROWS * (D_MODEL / 4)) / 256;      // 8192
    conv_aug_kernel<true><<<xblocks, 256>>>(x, xaug, ROWS);

    // QKV projections (tensor cores), head-major scatter
    dim3 ggrid(ROWS / 128, D_MODEL / 128);
    gemm_mma_kernel<true><<<ggrid, 256>>>(xaug, waug + 0 * wstride, bq, q);
    gemm_mma_kernel<true><<<ggrid, 256>>>(xaug, waug + 1 * wstride, bk, k);
    gemm_mma_kernel<true><<<ggrid, 256>>>(xaug, waug + 2 * wstride, bv, v);

    // Attention (fp32 SIMT flash)
    dim3 agrid(S_LEN / 64, BATCH * NHEAD);
    attn_kernel<<<agrid, 256>>>(q, k, v, att);

    // Output projection: convert att (reuse xaug buffer), then GEMM
    conv_aug_kernel<true><<<xblocks, 256>>>(att, xaug, ROWS);
    gemm_mma_kernel<false><<<ggrid, 256>>>(xaug, waug + 3 * wstride, bo, out);
}